// round 14
// baseline (speedup 1.0000x reference)
#include <cuda_runtime.h>
#include <cuda_bf16.h>
#include <cstdint>

// LocallyConnected1d: out[b,c,o] = (1/8) * sum_{i<64,k<8} x[b,i,4o+k] * w[c,i,o,k]
// x: [128, 64, 1028] fp32, w: [1, 64, 64, 256, 8] fp32, out: [128, 64, 256] fp32
//
// R12 o-grouped layout + R13 strength reduction + R14 software pipelining:
// cvt+STS(j+1) and LDG(j+2) are interleaved INTO the MMA(j) kk-loop, removing
// the serial convert phase from each warp's critical path. One barrier/chunk.

#define CINC  64
#define NCOUT 64
#define OD    256
#define LL    1028

#define NCHUNK  16              // K chunks of 32 (4 i-rows x 8 k)

#define A_ST   4128             // A-tile stride: 4KB + 32B stagger
#define B_ST   8224             // B-tile stride: 8KB + 32B stagger
#define BREG   (4 * A_ST)                  // 16512
#define STAGE_SIZE (BREG + 4 * B_ST)       // 49408
#define SMEM_BYTES (2 * STAGE_SIZE)        // 98816

#define EPI_BF 268              // stride 67 banks: epi STS conflict-free

static __device__ __forceinline__ uint32_t smem_u32(const void* p) {
    uint32_t a;
    asm("{ .reg .u64 t; cvta.to.shared.u64 t, %1; cvt.u32.u64 %0, t; }"
        : "=r"(a) : "l"(p));
    return a;
}

static __device__ __forceinline__ uint32_t f2tf32(float f) {
    uint32_t r;
    asm("cvt.rna.tf32.f32 %0, %1;" : "=r"(r) : "f"(f));
    return r;
}

static __device__ __forceinline__ uint4 cvt4(float4 v) {
    uint4 t;
    t.x = f2tf32(v.x);  t.y = f2tf32(v.y);
    t.z = f2tf32(v.z);  t.w = f2tf32(v.w);
    return t;
}

#define LDSM_X4(r, addr)                                                     \
    asm volatile("ldmatrix.sync.aligned.m8n8.x4.shared.b16 {%0,%1,%2,%3}, [%4];" \
        : "=r"((r)[0]), "=r"((r)[1]), "=r"((r)[2]), "=r"((r)[3]) : "r"(addr))

#define MMA_TF32(c, a, b0, b1)                                               \
    asm volatile("mma.sync.aligned.m16n8k8.row.col.f32.tf32.tf32.f32 "       \
        "{%0,%1,%2,%3}, {%4,%5,%6,%7}, {%8,%9}, {%0,%1,%2,%3};"              \
        : "+f"((c)[0]), "+f"((c)[1]), "+f"((c)[2]), "+f"((c)[3])             \
        : "r"((a)[0]), "r"((a)[1]), "r"((a)[2]), "r"((a)[3]),                \
          "r"(b0), "r"(b1))

__global__ __launch_bounds__(256, 2)
void lc1d_og4_kernel(const float* __restrict__ x,
                     const float* __restrict__ w,
                     float* __restrict__ out)
{
    extern __shared__ char smem[];
    const uint32_t sb = smem_u32(smem);

    const int o0    = blockIdx.x * 4;     // 64 o-groups
    const int bbase = blockIdx.y * 32;    // 4 b-quarters
    const int tid   = threadIdx.x;
    const int wid   = tid >> 5;
    const int lid   = tid & 31;

    const int o_w = wid >> 1;             // warp's o-tile (0..3)
    const int nh  = wid & 1;              // warp's n-half (0..1)

    float acc[2][4][4];
    #pragma unroll
    for (int mt = 0; mt < 2; mt++)
        #pragma unroll
        for (int nt = 0; nt < 4; nt++)
            #pragma unroll
            for (int r = 0; r < 4; r++)
                acc[mt][nt][r] = 0.0f;

    // ---- gather decomposition (R12) ----
    const int xm  = tid & 7;
    const int xms = xm > 4 ? 4 : xm;      // clamp keeps og=63 strip in bounds
    const int bx  = tid >> 3;
    const int wm  = tid & 7;
    const int pw  = tid >> 3;

    // gmem pointers (advanced by constant stride per loaded chunk)
    const float* xptr = x + ((size_t)(bbase + bx) * CINC) * LL
                          + (size_t)o0 * 4 + xms * 4;
    const float* wp0  = w + (((size_t)pw * CINC) * OD + o0) * 8 + wm * 4;
    const float* wp1  = wp0 + (size_t)32 * CINC * OD * 8;

    // ---- store-side precomputed offsets ----
    const uint32_t xs1 = (uint32_t)(xm * A_ST + bx * 128);
    const uint32_t xs2 = (uint32_t)((xm - 1) * A_ST + bx * 128);  // iff xm>=1
    const uint32_t kx  = (uint32_t)((bx & 7) << 4);
    const uint32_t kx2 = kx ^ 16u;
    const uint32_t wsb = (uint32_t)(BREG + (wm >> 1) * B_ST + pw * 128);
    const uint32_t kw  = ((uint32_t)((pw & 7) << 4)) ^ ((uint32_t)((wm & 1) << 4));

    // ---- ldsm precomputed bases ----
    const uint32_t lr = (uint32_t)(lid & 15);
    const uint32_t sk = ((uint32_t)(lid >> 4) << 4) ^ ((uint32_t)(lid & 7) << 4);
    const uint32_t baseA0 = sb + (uint32_t)(o_w * A_ST) + lr * 128;
    const uint32_t baseA1 = baseA0 + 16 * 128;
    const uint32_t baseB0 = sb + (uint32_t)(BREG + o_w * B_ST)
                               + (uint32_t)(nh * 32 + lr) * 128;
    const uint32_t baseB1 = baseB0 + 16 * 128;

    float4 xr[4], wr[8];

    // helpers (capture by reference)
    auto ldg_all = [&]() {
        #pragma unroll
        for (int it = 0; it < 4; it++)
            xr[it] = *reinterpret_cast<const float4*>(xptr + (size_t)it * LL);
        #pragma unroll
        for (int it = 0; it < 8; it++)
            wr[it] = *reinterpret_cast<const float4*>(
                ((it & 1) ? wp1 : wp0) + (size_t)(it >> 1) * (OD * 8));
    };
    auto advance = [&]() {
        xptr += 4 * LL;
        wp0  += 4 * (OD * 8);
        wp1  += 4 * (OD * 8);
    };
    auto store_x = [&](char* stgp) {
        #pragma unroll
        for (int it = 0; it < 4; it++) {
            uint4 t = cvt4(xr[it]);
            if (xm < 4)
                *reinterpret_cast<uint4*>(
                    stgp + xs1 + (kx ^ (uint32_t)(it * 32))) = t;
            if (xm >= 1 && xm <= 4)
                *reinterpret_cast<uint4*>(
                    stgp + xs2 + (kx2 ^ (uint32_t)(it * 32))) = t;
        }
    };
    auto store_w4 = [&](char* stgp, int base) {
        #pragma unroll
        for (int q = 0; q < 4; q++) {
            int it = base + q;
            uint4 t = cvt4(wr[it]);
            *reinterpret_cast<uint4*>(
                stgp + wsb + (uint32_t)((it & 1) * 4096)
                     + (kw ^ (uint32_t)((it >> 1) * 32))) = t;
        }
    };

    // ---- prologue: load chunk0, stage it, load chunk1 ----
    ldg_all();                       // chunk 0
    store_x(smem);                   // stage 0
    store_w4(smem, 0);
    store_w4(smem, 4);
    advance();
    ldg_all();                       // chunk 1 (latency hidden by BAR + MMA0)
    __syncthreads();

    // ---- main loop: MMA(j) interleaved with cvt/STS(j+1) and LDG(j+2) ----
    #pragma unroll 2
    for (int j = 0; j < NCHUNK; j++) {
        const uint32_t stg = (uint32_t)(j & 1) * STAGE_SIZE;
        char* const nstgp = smem + ((uint32_t)((j + 1) & 1) * STAGE_SIZE);
        const bool do_cvt = (j + 1 < NCHUNK);
        const bool do_ldg = (j + 2 < NCHUNK);

        #pragma unroll
        for (int kk = 0; kk < 4; kk++) {
            const uint32_t ko = sk ^ (uint32_t)(kk * 32);
            uint32_t a[2][4], b[2][4];
            LDSM_X4(a[0], baseA0 + stg + ko);
            LDSM_X4(a[1], baseA1 + stg + ko);
            LDSM_X4(b[0], baseB0 + stg + ko);
            LDSM_X4(b[1], baseB1 + stg + ko);

            // interleaved pipeline work (fills the ldsm->MMA shadow)
            if (do_cvt) {
                if (kk == 0)      store_x(nstgp);
                else if (kk == 1) store_w4(nstgp, 0);
                else if (kk == 2) store_w4(nstgp, 4);
            }
            if (do_ldg && kk == 3) {
                advance();
                ldg_all();       // chunk j+2; covered until cvt at iter j+1
            }

            #pragma unroll
            for (int mt = 0; mt < 2; mt++) {
                #pragma unroll
                for (int nt = 0; nt < 4; nt++) {
                    const int nt2 = nt >> 1;
                    const int sel = nt & 1;
                    MMA_TF32(acc[mt][nt], a[mt],
                             b[nt2][sel], b[nt2][sel + 2]);
                }
            }
        }

        __syncthreads();   // end-of-chunk: all warps done reading stage j&1
                           // and writing stage (j+1)&1
    }

    // ---- epilogue: stage acc in SMEM [b][c][o'] then STG.128 along o ----
    float* epi = reinterpret_cast<float*>(smem);
    const float scale = 0.125f;
    {
        const int rr = lid >> 2;
        const int c2 = (lid & 3) * 2;
        #pragma unroll
        for (int mt = 0; mt < 2; mt++)
            #pragma unroll
            for (int nt = 0; nt < 4; nt++)
                #pragma unroll
                for (int r = 0; r < 4; r++) {
                    int bb = mt * 16 + rr + ((r >> 1) & 1) * 8;
                    int cc = nh * 32 + nt * 8 + c2 + (r & 1);
                    epi[bb * EPI_BF + cc * 4 + o_w] = acc[mt][nt][r] * scale;
                }
    }
    __syncthreads();

    #pragma unroll
    for (int r = 0; r < 8; r++) {
        int idx = tid + r * 256;          // 0..2047
        int bb  = idx >> 6;
        int cc  = idx & 63;
        float4 v = *reinterpret_cast<const float4*>(epi + bb * EPI_BF + cc * 4);
        *reinterpret_cast<float4*>(
            out + ((size_t)(bbase + bb) * NCOUT + cc) * OD + o0) = v;
    }
}

extern "C" void kernel_launch(void* const* d_in, const int* in_sizes, int n_in,
                              void* d_out, int out_size) {
    const float* x = (const float*)d_in[0];
    const float* w = (const float*)d_in[1];
    float* out = (float*)d_out;

    static int configured = 0;
    if (!configured) {
        cudaFuncSetAttribute(lc1d_og4_kernel,
                             cudaFuncAttributeMaxDynamicSharedMemorySize, SMEM_BYTES);
        configured = 1;
    }
    dim3 grid(OD / 4, 4);
    lc1d_og4_kernel<<<grid, 256, SMEM_BYTES>>>(x, w, out);
}